// round 5
// baseline (speedup 1.0000x reference)
#include <cuda_runtime.h>
#include <cuda_bf16.h>
#include <cstdint>

// Problem constants
#define N_   32
#define C_   64
#define T_   300
#define V_   25
#define O_   128
#define TO_  150
#define TV_  7500      // T_*V_
#define TOV_ 3750      // TO_*V_
#define KT_  9
#define KKE_ 576       // C_*KT_  (effective K after gcn/tcn fusion)

// Scratch (static device allocations — allowed)
__device__ float g_Asum[V_ * V_];
__device__ float g_agg [N_ * C_ * T_ * V_];          // 61.4 MB
__device__ float g_xtcn[N_ * O_ * TO_ * V_];         // 61.4 MB
__device__ float g_Weff[KKE_ * O_];                  // [kk=(c*9+k)][o]
__device__ float g_beff[O_ * TO_];                   // [o][t]
// 18 pre-swizzled bf16 A-tile images: e in [0,9) = W_hi blocks, [9,18) = W_lo
__device__ __align__(16) unsigned short g_Wext[18 * 128 * 64];
__device__ float g_scale[O_];
__device__ float g_shift[O_];

// ---------------- PTX helpers (baseline sm_80-level: ldmatrix + mma.sync) ---
__device__ __forceinline__ uint32_t smem_u32(const void* p) {
    uint32_t a;
    asm("{ .reg .u64 t; cvta.to.shared.u64 t, %1; cvt.u32.u64 %0, t; }" : "=r"(a) : "l"(p));
    return a;
}
__device__ __forceinline__ void ldsm_x4(uint32_t* r, uint32_t addr) {
    asm volatile("ldmatrix.sync.aligned.m8n8.x4.shared.b16 {%0,%1,%2,%3}, [%4];"
                 : "=r"(r[0]), "=r"(r[1]), "=r"(r[2]), "=r"(r[3]) : "r"(addr));
}
__device__ __forceinline__ void ldsm_x2(uint32_t* r, uint32_t addr) {
    asm volatile("ldmatrix.sync.aligned.m8n8.x2.shared.b16 {%0,%1}, [%2];"
                 : "=r"(r[0]), "=r"(r[1]) : "r"(addr));
}
__device__ __forceinline__ void mma_bf16(float* d, const uint32_t* a, const uint32_t* b) {
    asm volatile(
        "mma.sync.aligned.m16n8k16.row.col.f32.bf16.bf16.f32 "
        "{%0,%1,%2,%3}, {%4,%5,%6,%7}, {%8,%9}, {%0,%1,%2,%3};"
        : "+f"(d[0]), "+f"(d[1]), "+f"(d[2]), "+f"(d[3])
        : "r"(a[0]), "r"(a[1]), "r"(a[2]), "r"(a[3]), "r"(b[0]), "r"(b[1]));
}
// SW128 with 128B rows reduces to: addr = row*128 + (col ^ ((row&7)<<4))
#define SWZ128(x) ((x) ^ (((x) >> 3) & 0x70))

// ---------------------------------------------------------------------------
// K0: A_sum
// ---------------------------------------------------------------------------
__global__ void k_asum(const float* __restrict__ A_parts,
                       const float* __restrict__ ei) {
    int i = threadIdx.x;
    if (i < V_ * V_) {
        float s = 0.f;
        #pragma unroll
        for (int p = 0; p < 3; p++) s += A_parts[p * V_ * V_ + i] * ei[p];
        g_Asum[i] = s;
    }
}

// ---------------------------------------------------------------------------
// K1: agg[n,c,t,w] = sum_v x[n,c,t,v] * A_sum[v][w]
// ---------------------------------------------------------------------------
__global__ void __launch_bounds__(256) k_agg(const float* __restrict__ x) {
    __shared__ float As[V_ * V_];
    for (int i = threadIdx.x; i < V_ * V_; i += 256) As[i] = g_Asum[i];
    __syncthreads();
    int idx = blockIdx.x * 256 + threadIdx.x;
    int w = idx % V_;
    int row = idx / V_;
    const float* xr = x + (size_t)row * V_;
    float s = 0.f;
    #pragma unroll
    for (int v = 0; v < V_; v++) s += xr[v] * As[v * V_ + w];
    g_agg[idx] = s;
}

// ---------------------------------------------------------------------------
// K2a: W_eff[(c*9+k)][o] = sum_{o2} tcn_w[o,o2,k] * gcn_w[o2,c]
// ---------------------------------------------------------------------------
__global__ void __launch_bounds__(128) k_weff(const float* __restrict__ tcn_w,
                                              const float* __restrict__ gcn_w) {
    __shared__ float gc[O_];
    int ck = blockIdx.x;
    int c = ck / KT_, k = ck % KT_;
    int o = threadIdx.x;
    gc[o] = gcn_w[o * C_ + c];
    __syncthreads();
    const float* wrow = tcn_w + (size_t)o * O_ * KT_ + k;
    float s = 0.f;
    #pragma unroll 8
    for (int o2 = 0; o2 < O_; o2++) s += wrow[o2 * KT_] * gc[o2];
    g_Weff[ck * O_ + o] = s;
}

// ---------------------------------------------------------------------------
// K2b: bias_eff — parallel: grid=O_, block=128
// ---------------------------------------------------------------------------
__global__ void __launch_bounds__(128) k_beff(const float* __restrict__ tcn_w,
                                              const float* __restrict__ gcn_b,
                                              const float* __restrict__ tcn_b) {
    __shared__ float red[128];
    __shared__ float Bk[KT_];
    int o = blockIdx.x, o2 = threadIdx.x;
    float gb = gcn_b[o2];
    const float* wrow = tcn_w + ((size_t)o * O_ + o2) * KT_;
    #pragma unroll
    for (int k = 0; k < KT_; k++) {
        red[o2] = wrow[k] * gb;
        __syncthreads();
        for (int st = 64; st > 0; st >>= 1) {
            if (o2 < st) red[o2] += red[o2 + st];
            __syncthreads();
        }
        if (o2 == 0) Bk[k] = red[0];
        __syncthreads();
    }
    float tb = tcn_b[o];
    for (int t = threadIdx.x; t < TO_; t += 128) {
        float s = tb;
        #pragma unroll
        for (int k = 0; k < KT_; k++) {
            int tp = 2 * t + k - 4;
            if (tp >= 0 && tp < T_) s += Bk[k];
        }
        g_beff[o * TO_ + t] = s;
    }
}

// ---------------------------------------------------------------------------
// K2c: W_ext — pre-swizzled bf16 A-tile images (hi: e<9, lo: e>=9).
// Image e: 128 o-rows x 64 k-cols, byte_off = SWZ128(o*128 + kl*2).
// ---------------------------------------------------------------------------
__global__ void __launch_bounds__(256) k_wext() {
    int e = blockIdx.x;
    int kb = (e % 9) * 64;
    bool lo = (e >= 9);
    unsigned short* dst = g_Wext + e * 8192;
    for (int i = threadIdx.x; i < 8192; i += 256) {
        int o = i >> 6;
        int kl = i & 63;
        float w = g_Weff[(kb + kl) * O_ + o];
        __nv_bfloat16 h = __float2bfloat16(w);
        __nv_bfloat16 v = h;
        if (lo) v = __float2bfloat16(w - __bfloat162float(h));
        unsigned short bits = *reinterpret_cast<unsigned short*>(&v);
        uint32_t boff = SWZ128((uint32_t)(o * 128 + kl * 2));
        dst[boff >> 1] = bits;
    }
}

// ---------------------------------------------------------------------------
// K3: fused gcn+tcn via mma.sync bf16 (HMMA), 3-term error compensation:
//   D = Ahi*Bhi + Ahi*Blo + Alo*Bhi     (residual Alo*Blo ~ 2^-18 rel)
// Per CTA: 128(o) x 128(s).  8 warps in 2x4; warp tile 64x32.
// 9 K-blocks of 64; per block: copy Ahi/Alo images, gather B once -> hi/lo.
// ---------------------------------------------------------------------------
__global__ void __launch_bounds__(256, 2) k_tcn_mma() {
    __shared__ __align__(16) unsigned char sAhi[16384];
    __shared__ __align__(16) unsigned char sAlo[16384];
    __shared__ __align__(16) unsigned char sBhi[16384];
    __shared__ __align__(16) unsigned char sBlo[16384];

    int tid = threadIdx.x;
    int lane = tid & 31;
    int wid = tid >> 5;
    int wm = wid >> 2;        // 0..1
    int wn = wid & 3;         // 0..3
    int n = blockIdx.y;
    int s0 = blockIdx.x * 128;
    const float* In = g_agg + (size_t)n * C_ * TV_;

    // gather coords (thread covers s-row r, k-half)
    int r = tid & 127;
    int half = tid >> 7;
    int s = s0 + r;
    int my_t2 = (s < TOV_) ? (s / V_) * 2 : -100000;
    int my_v  = (s < TOV_) ? (s % V_) : 0;
    int xors = (r & 7) << 4;

    // mma lane addressing (SW128 with 128B rows: col ^ ((row&7)<<4))
    uint32_t aHiBase = smem_u32(sAhi), aLoBase = smem_u32(sAlo);
    uint32_t bHiBase = smem_u32(sBhi), bLoBase = smem_u32(sBlo);
    int la_row = ((lane >> 3) & 1) * 8 + (lane & 7);
    int la_col = ((lane >> 4) & 1) * 16;
    int lb_col = ((lane >> 3) & 1) * 16;
    uint32_t xorm = (uint32_t)((lane & 7) << 4);
    uint32_t aRow = (uint32_t)(wm * 64 + la_row) * 128;
    uint32_t bRow = (uint32_t)(wn * 32 + (lane & 7)) * 128;

    float acc[4][4][4] = {};

    for (int blk = 0; blk < 9; blk++) {
        // copy A images (16KB each)
        const uint4* srcH = (const uint4*)(g_Wext + blk * 8192);
        const uint4* srcL = (const uint4*)(g_Wext + (9 + blk) * 8192);
        uint4* dH = (uint4*)sAhi;
        uint4* dL = (uint4*)sAlo;
        #pragma unroll
        for (int i = 0; i < 4; i++) {
            dH[tid + 256 * i] = srcH[tid + 256 * i];
            dL[tid + 256 * i] = srcL[tid + 256 * i];
        }
        // gather B once, split into hi/lo
        int kb = blk * 64;
        #pragma unroll
        for (int jj = 0; jj < 8; jj++) {
            int j = half * 32 + jj * 4;
            float v[4];
            #pragma unroll
            for (int q = 0; q < 4; q++) {
                int k = kb + j + q;
                int ci = k / 9, kk = k - ci * 9;
                int tp = my_t2 + kk - 4;
                v[q] = ((unsigned)tp < (unsigned)T_) ? In[(ci * T_ + tp) * V_ + my_v] : 0.f;
            }
            uint32_t hip[2], lop[2];
            #pragma unroll
            for (int p = 0; p < 2; p++) {
                __nv_bfloat16 h0 = __float2bfloat16(v[2 * p]);
                __nv_bfloat16 h1 = __float2bfloat16(v[2 * p + 1]);
                __nv_bfloat16 l0 = __float2bfloat16(v[2 * p]     - __bfloat162float(h0));
                __nv_bfloat16 l1 = __float2bfloat16(v[2 * p + 1] - __bfloat162float(h1));
                hip[p] = (uint32_t)*reinterpret_cast<unsigned short*>(&h0) |
                         ((uint32_t)*reinterpret_cast<unsigned short*>(&h1) << 16);
                lop[p] = (uint32_t)*reinterpret_cast<unsigned short*>(&l0) |
                         ((uint32_t)*reinterpret_cast<unsigned short*>(&l1) << 16);
            }
            uint32_t off = (uint32_t)(r * 128 + ((j * 2) ^ xors));
            *reinterpret_cast<uint2*>(sBhi + off) = make_uint2(hip[0], hip[1]);
            *reinterpret_cast<uint2*>(sBlo + off) = make_uint2(lop[0], lop[1]);
        }
        __syncthreads();

        // MMA over this 64-K block: 4 k-steps of 16
        #pragma unroll
        for (int ks = 0; ks < 4; ks++) {
            uint32_t bh[4][2], bl[4][2];
            uint32_t cb = ((uint32_t)(ks * 32 + lb_col)) ^ xorm;
            #pragma unroll
            for (int nt = 0; nt < 4; nt++) {
                ldsm_x2(bh[nt], bHiBase + bRow + nt * 1024 + cb);
                ldsm_x2(bl[nt], bLoBase + bRow + nt * 1024 + cb);
            }
            uint32_t ca = ((uint32_t)(ks * 32 + la_col)) ^ xorm;
            #pragma unroll
            for (int mt = 0; mt < 4; mt++) {
                uint32_t ah[4], al[4];
                ldsm_x4(ah, aHiBase + aRow + mt * 2048 + ca);
                ldsm_x4(al, aLoBase + aRow + mt * 2048 + ca);
                #pragma unroll
                for (int nt = 0; nt < 4; nt++) {
                    mma_bf16(acc[mt][nt], ah, bh[nt]);
                    mma_bf16(acc[mt][nt], ah, bl[nt]);
                    mma_bf16(acc[mt][nt], al, bh[nt]);
                }
            }
        }
        __syncthreads();
    }

    // Epilogue: + beff[o][t], direct stores
    float* Out = g_xtcn + (size_t)n * O_ * TOV_;
    int qr = lane >> 2;
    int qc = (lane & 3) * 2;
    #pragma unroll
    for (int mt = 0; mt < 4; mt++) {
        #pragma unroll
        for (int hh = 0; hh < 2; hh++) {
            int o = wm * 64 + mt * 16 + qr + hh * 8;
            float* orow = Out + (size_t)o * TOV_;
            const float* be = g_beff + o * TO_;
            #pragma unroll
            for (int nt = 0; nt < 4; nt++) {
                int s1 = s0 + wn * 32 + nt * 8 + qc;
                if (s1 < TOV_)     orow[s1]     = acc[mt][nt][hh * 2 + 0] + be[s1 / V_];
                if (s1 + 1 < TOV_) orow[s1 + 1] = acc[mt][nt][hh * 2 + 1] + be[(s1 + 1) / V_];
            }
        }
    }
}

// ---------------------------------------------------------------------------
// K4: BN stats
// ---------------------------------------------------------------------------
__global__ void __launch_bounds__(256) k_stats(const float* __restrict__ gamma,
                                               const float* __restrict__ beta) {
    __shared__ double sh[512];
    int o = blockIdx.x;
    double s = 0.0, s2 = 0.0;
    for (int nn = 0; nn < N_; nn++) {
        const float* p = g_xtcn + ((size_t)nn * O_ + o) * TOV_;
        for (int i = threadIdx.x; i < TOV_; i += 256) {
            float v = p[i];
            s  += (double)v;
            s2 += (double)v * (double)v;
        }
    }
    sh[threadIdx.x] = s;
    sh[256 + threadIdx.x] = s2;
    __syncthreads();
    for (int st = 128; st > 0; st >>= 1) {
        if (threadIdx.x < st) {
            sh[threadIdx.x] += sh[threadIdx.x + st];
            sh[256 + threadIdx.x] += sh[256 + threadIdx.x + st];
        }
        __syncthreads();
    }
    if (threadIdx.x == 0) {
        double cnt = (double)N_ * (double)TOV_;
        double mean = sh[0] / cnt;
        double var = sh[256] / cnt - mean * mean;
        float rstd = (float)(1.0 / sqrt(var + 1e-5));
        float sc = gamma[o] * rstd;
        g_scale[o] = sc;
        g_shift[o] = beta[o] - (float)mean * sc;
    }
}

// ---------------------------------------------------------------------------
// K5: final — residual GEMM fused with BN affine + add + ReLU
// ---------------------------------------------------------------------------
__global__ void __launch_bounds__(256) k_final(const float* __restrict__ x,
                                               const float* __restrict__ W,
                                               const float* __restrict__ bias,
                                               float* __restrict__ out) {
    __shared__ float Wt[C_][132];
    __shared__ float Is[16][128];
    __shared__ int st2[128];
    __shared__ int sv[128];
    int tid = threadIdx.x;
    int n = blockIdx.y;
    int s0 = blockIdx.x * 128;
    const float* In = x + (size_t)n * C_ * TV_;

    #pragma unroll
    for (int i = 0; i < 32; i++) {
        int e = i * 256 + tid;
        int c = e & 63, o = e >> 6;
        Wt[c][o] = W[o * C_ + c];
    }
    if (tid < 128) {
        int s = s0 + tid;
        if (s < TOV_) { st2[tid] = (s / V_) * 2; sv[tid] = s % V_; }
        else          { st2[tid] = 0;            sv[tid] = 0; }
    }
    __syncthreads();

    int myS = tid & 127;
    int my_t2 = st2[myS];
    int my_v  = sv[myS];
    int kk_par = tid >> 7;
    int tx = tid & 15, ty = tid >> 4;
    float acc[8][8] = {};

    for (int kt = 0; kt < 4; kt++) {
        __syncthreads();
        #pragma unroll
        for (int i = 0; i < 8; i++) {
            int cl = 2 * i + kk_par;
            int c = kt * 16 + cl;
            Is[cl][myS] = In[(c * T_ + my_t2) * V_ + my_v];
        }
        __syncthreads();
        #pragma unroll
        for (int c = 0; c < 16; c++) {
            float4 a0 = *(const float4*)&Wt[kt * 16 + c][ty * 4];
            float4 a1 = *(const float4*)&Wt[kt * 16 + c][64 + ty * 4];
            float4 b0 = *(const float4*)&Is[c][tx * 4];
            float4 b1 = *(const float4*)&Is[c][64 + tx * 4];
            float a[8] = {a0.x, a0.y, a0.z, a0.w, a1.x, a1.y, a1.z, a1.w};
            float b[8] = {b0.x, b0.y, b0.z, b0.w, b1.x, b1.y, b1.z, b1.w};
            #pragma unroll
            for (int i = 0; i < 8; i++)
                #pragma unroll
                for (int j = 0; j < 8; j++)
                    acc[i][j] += a[i] * b[j];
        }
    }

    const float* Tcn = g_xtcn + (size_t)n * O_ * TOV_;
    #pragma unroll
    for (int i = 0; i < 8; i++) {
        int o = (i < 4) ? (ty * 4 + i) : (64 + ty * 4 + i - 4);
        float bo = __ldg(&bias[o]);
        float sc = g_scale[o];
        float sh = g_shift[o];
        #pragma unroll
        for (int j = 0; j < 8; j++) {
            int s = s0 + ((j < 4) ? (tx * 4 + j) : (64 + tx * 4 + j - 4));
            if (s < TOV_) {
                float bn = Tcn[o * TOV_ + s] * sc + sh;
                float v = bn + acc[i][j] + bo;
                out[((size_t)n * O_ + o) * TOV_ + s] = fmaxf(v, 0.f);
            }
        }
    }
}

// ---------------------------------------------------------------------------
extern "C" void kernel_launch(void* const* d_in, const int* in_sizes, int n_in,
                              void* d_out, int out_size) {
    const float* x       = (const float*)d_in[0];
    const float* A_parts = (const float*)d_in[1];
    const float* ei      = (const float*)d_in[2];
    const float* gcn_w   = (const float*)d_in[3];
    const float* gcn_b   = (const float*)d_in[4];
    const float* tcn_w   = (const float*)d_in[5];
    const float* tcn_b   = (const float*)d_in[6];
    const float* bn_g    = (const float*)d_in[7];
    const float* bn_b    = (const float*)d_in[8];
    const float* res_w   = (const float*)d_in[9];
    const float* res_b   = (const float*)d_in[10];
    float* out = (float*)d_out;

    k_asum<<<1, 640>>>(A_parts, ei);
    k_agg<<<(N_ * C_ * T_ * V_) / 256, 256>>>(x);
    k_weff<<<KKE_, 128>>>(tcn_w, gcn_w);
    k_beff<<<O_, 128>>>(tcn_w, gcn_b, tcn_b);
    k_wext<<<18, 256>>>();
    dim3 gtcn((TOV_ + 127) / 128, N_);
    k_tcn_mma<<<gtcn, 256>>>();
    k_stats<<<O_, 256>>>(bn_g, bn_b);
    dim3 gfin((TOV_ + 127) / 128, N_);
    k_final<<<gfin, 256>>>(x, res_w, res_b, out);
}

// round 6
// speedup vs baseline: 1.4583x; 1.4583x over previous
#include <cuda_runtime.h>
#include <cuda_bf16.h>
#include <cstdint>

// Problem constants
#define N_   32
#define C_   64
#define T_   300
#define V_   25
#define O_   128
#define TO_  150
#define TV_  7500      // T_*V_
#define TOV_ 3750      // TO_*V_
#define KT_  9
#define KKE_ 576       // C_*KT_

// Phase-split transposed agg layout: [n][v][row][c], row<224: even phase
// (t_in = 2*(row-2)), row>=224: odd phase (t_in = 2*(row-224-2)+1).
// Rows with invalid t_in are zero. 128-byte rows, pre-swizzled (SW128).
#define ROWS_ 448

__device__ float g_Asum[V_ * V_];
__device__ float g_xtcn[N_ * O_ * TO_ * V_];         // 61.4 MB fp32
__device__ float g_Weff[KKE_ * O_];                  // [kk=(c*9+k)][o]
__device__ float g_beff[O_ * TO_];                   // [o][t]
__device__ __align__(16) unsigned short g_aggBH[(size_t)N_ * V_ * ROWS_ * 64]; // bf16 hi
__device__ __align__(16) unsigned short g_aggBL[(size_t)N_ * V_ * ROWS_ * 64]; // bf16 lo
__device__ __align__(16) unsigned short g_WtapH[9 * 128 * 64]; // per-tap [o][c] swizzled
__device__ __align__(16) unsigned short g_WtapL[9 * 128 * 64];
__device__ float g_scale[O_];
__device__ float g_shift[O_];

// ---------------- PTX helpers (baseline: ldmatrix + mma.sync bf16) ----------
__device__ __forceinline__ uint32_t smem_u32(const void* p) {
    uint32_t a;
    asm("{ .reg .u64 t; cvta.to.shared.u64 t, %1; cvt.u32.u64 %0, t; }" : "=r"(a) : "l"(p));
    return a;
}
__device__ __forceinline__ void ldsm_x4(uint32_t* r, uint32_t addr) {
    asm volatile("ldmatrix.sync.aligned.m8n8.x4.shared.b16 {%0,%1,%2,%3}, [%4];"
                 : "=r"(r[0]), "=r"(r[1]), "=r"(r[2]), "=r"(r[3]) : "r"(addr));
}
__device__ __forceinline__ void ldsm_x2(uint32_t* r, uint32_t addr) {
    asm volatile("ldmatrix.sync.aligned.m8n8.x2.shared.b16 {%0,%1}, [%2];"
                 : "=r"(r[0]), "=r"(r[1]) : "r"(addr));
}
__device__ __forceinline__ void mma_bf16(float* d, const uint32_t* a, const uint32_t* b) {
    asm volatile(
        "mma.sync.aligned.m16n8k16.row.col.f32.bf16.bf16.f32 "
        "{%0,%1,%2,%3}, {%4,%5,%6,%7}, {%8,%9}, {%0,%1,%2,%3};"
        : "+f"(d[0]), "+f"(d[1]), "+f"(d[2]), "+f"(d[3])
        : "r"(a[0]), "r"(a[1]), "r"(a[2]), "r"(a[3]), "r"(b[0]), "r"(b[1]));
}
#define SWZ128(x) ((x) ^ (((x) >> 3) & 0x70))

// ---------------------------------------------------------------------------
// K0: A_sum
// ---------------------------------------------------------------------------
__global__ void k_asum(const float* __restrict__ A_parts,
                       const float* __restrict__ ei) {
    int i = threadIdx.x;
    if (i < V_ * V_) {
        float s = 0.f;
        #pragma unroll
        for (int p = 0; p < 3; p++) s += A_parts[p * V_ * V_ + i] * ei[p];
        g_Asum[i] = s;
    }
}

// ---------------------------------------------------------------------------
// K1: agg in phase-split transposed bf16 hi/lo layout.
// Block = (row, n). Computes agg[n,c,t_in,v] for all (v,c), writes
// g_aggB{H,L}[n][v][row][swizzled c]. Invalid t_in -> zeros.
// ---------------------------------------------------------------------------
__global__ void __launch_bounds__(256) k_aggp(const float* __restrict__ x) {
    __shared__ float sx[1600];            // [c*25 + w]
    __shared__ float As[625];             // [w*25 + v]
    __shared__ __align__(16) unsigned short souts[2][1600]; // [arr][v*64 + c]
    int row = blockIdx.x, n = blockIdx.y, tid = threadIdx.x;
    int phase = (row >= 224) ? 1 : 0;
    int e = phase ? (row - 224) : row;
    int t_in = 2 * (e - 2) + phase;
    bool valid = (t_in >= 0) && (t_in < T_);

    if (valid) {
        for (int i = tid; i < 625; i += 256) As[i] = g_Asum[i];
        const float* xb = x + ((size_t)n * C_) * TV_ + t_in * V_;
        for (int i = tid; i < 1600; i += 256) {
            int c = i / 25, w = i - c * 25;
            sx[i] = xb[c * TV_ + w];
        }
        __syncthreads();
        for (int i = tid; i < 1600; i += 256) {
            int v = i >> 6, c = i & 63;
            float s = 0.f;
            #pragma unroll
            for (int w = 0; w < 25; w++) s += sx[c * 25 + w] * As[w * 25 + v];
            __nv_bfloat16 h = __float2bfloat16(s);
            __nv_bfloat16 l = __float2bfloat16(s - __bfloat162float(h));
            souts[0][v * 64 + c] = *reinterpret_cast<unsigned short*>(&h);
            souts[1][v * 64 + c] = *reinterpret_cast<unsigned short*>(&l);
        }
        __syncthreads();
        int r7 = row & 7;
        for (int j = tid; j < 400; j += 256) {
            int v = j >> 4, qq = j & 15, arr = qq >> 3, q = qq & 7;
            uint4 val = *(const uint4*)&souts[arr][v * 64 + ((q ^ r7) << 3)];
            unsigned short* base = arr ? g_aggBL : g_aggBH;
            *((uint4*)(base + (((size_t)(n * 25 + v) * ROWS_ + row) << 6)) + q) = val;
        }
    } else {
        for (int j = tid; j < 400; j += 256) {
            int v = j >> 4, qq = j & 15, arr = qq >> 3, q = qq & 7;
            unsigned short* base = arr ? g_aggBL : g_aggBH;
            *((uint4*)(base + (((size_t)(n * 25 + v) * ROWS_ + row) << 6)) + q) =
                make_uint4(0, 0, 0, 0);
        }
    }
}

// ---------------------------------------------------------------------------
// K2a: W_eff[(c*9+k)][o] = sum_{o2} tcn_w[o,o2,k] * gcn_w[o2,c]
// ---------------------------------------------------------------------------
__global__ void __launch_bounds__(128) k_weff(const float* __restrict__ tcn_w,
                                              const float* __restrict__ gcn_w) {
    __shared__ float gc[O_];
    int ck = blockIdx.x;
    int c = ck / KT_, k = ck % KT_;
    int o = threadIdx.x;
    gc[o] = gcn_w[o * C_ + c];
    __syncthreads();
    const float* wrow = tcn_w + (size_t)o * O_ * KT_ + k;
    float s = 0.f;
    #pragma unroll 8
    for (int o2 = 0; o2 < O_; o2++) s += wrow[o2 * KT_] * gc[o2];
    g_Weff[ck * O_ + o] = s;
}

// ---------------------------------------------------------------------------
// K2b: bias_eff — grid=O_, block=128
// ---------------------------------------------------------------------------
__global__ void __launch_bounds__(128) k_beff(const float* __restrict__ tcn_w,
                                              const float* __restrict__ gcn_b,
                                              const float* __restrict__ tcn_b) {
    __shared__ float red[128];
    __shared__ float Bk[KT_];
    int o = blockIdx.x, o2 = threadIdx.x;
    float gb = gcn_b[o2];
    const float* wrow = tcn_w + ((size_t)o * O_ + o2) * KT_;
    #pragma unroll
    for (int k = 0; k < KT_; k++) {
        red[o2] = wrow[k] * gb;
        __syncthreads();
        for (int st = 64; st > 0; st >>= 1) {
            if (o2 < st) red[o2] += red[o2 + st];
            __syncthreads();
        }
        if (o2 == 0) Bk[k] = red[0];
        __syncthreads();
    }
    float tb = tcn_b[o];
    for (int t = threadIdx.x; t < TO_; t += 128) {
        float s = tb;
        #pragma unroll
        for (int k = 0; k < KT_; k++) {
            int tp = 2 * t + k - 4;
            if (tp >= 0 && tp < T_) s += Bk[k];
        }
        g_beff[o * TO_ + t] = s;
    }
}

// ---------------------------------------------------------------------------
// K2c: per-tap A images [o rows][c cols], 128B rows, SW128 swizzled, hi/lo.
// ---------------------------------------------------------------------------
__global__ void __launch_bounds__(256) k_wtap() {
    int k = blockIdx.x;
    for (int i = threadIdx.x; i < 8192; i += 256) {
        int o = i >> 6, c = i & 63;
        float w = g_Weff[(c * KT_ + k) * O_ + o];
        __nv_bfloat16 h = __float2bfloat16(w);
        __nv_bfloat16 l = __float2bfloat16(w - __bfloat162float(h));
        uint32_t boff = SWZ128((uint32_t)(o * 128 + c * 2));
        g_WtapH[k * 8192 + (boff >> 1)] = *reinterpret_cast<unsigned short*>(&h);
        g_WtapL[k * 8192 + (boff >> 1)] = *reinterpret_cast<unsigned short*>(&l);
    }
}

// ---------------------------------------------------------------------------
// K3: fused gcn+tcn, tap-shift HMMA. CTA = (t-block of 64, v, n).
// B tile loaded once (coalesced copy of phase-split layout); 9 taps reuse it
// with a row shift. A tap images streamed from L2. 3-pass bf16 compensation.
// ---------------------------------------------------------------------------
#define BH_OFF 0
#define BL_OFF 18432
#define AH_OFF 36864
#define AL_OFF 53248
#define SMEM_TOT 69632

__global__ void __launch_bounds__(256) k_tcn_mma() {
    extern __shared__ __align__(16) unsigned char smem[];
    int tid = threadIdx.x, lane = tid & 31, wid = tid >> 5;
    int wm = wid >> 2, wn = wid & 3;
    int t0 = blockIdx.x * 64;
    int v = blockIdx.y;
    int n = blockIdx.z;
    uint32_t sbase = smem_u32(smem);

    // ---- B copy: even rows t0..t0+67 -> smem rows 0..67; odd -> 72..138
    const unsigned short* gBH = g_aggBH + ((size_t)(n * 25 + v) * ROWS_) * 64;
    const unsigned short* gBL = g_aggBL + ((size_t)(n * 25 + v) * ROWS_) * 64;
    for (int j = tid; j < 2160; j += 256) {
        int p = (j >= 1080) ? 1 : 0;
        int r = p ? (j - 1080) : j;
        int srow, grow;
        if (r < 544) { srow = r >> 3; grow = t0 + srow; }
        else { int rr = (r - 544) >> 3; srow = 72 + rr; grow = 224 + t0 + rr; }
        int q = r & 7;
        const uint4* src = (const uint4*)((p ? gBL : gBH) + (size_t)grow * 64) + q;
        *((uint4*)(smem + (p ? BL_OFF : BH_OFF) + srow * 128) + q) = *src;
    }

    // fragment addressing
    int la_row = ((lane >> 3) & 1) * 8 + (lane & 7);
    uint32_t xorA = (uint32_t)((lane & 7) << 4);
    uint32_t la_col = ((lane >> 4) & 1) * 16;
    uint32_t lb_col = ((lane >> 3) & 1) * 16;
    uint32_t aRow = (uint32_t)(wm * 64 + la_row) * 128;

    float acc[4][2][4] = {};

    for (int k = 0; k < 9; k++) {
        __syncthreads();   // B ready (k=0) / prev-tap ldsm done (k>0)
        // A tap copy (hi+lo, 32KB)
        for (int j = tid; j < 2048; j += 256) {
            int p = j >> 10, idx = j & 1023;
            const uint4* src = (const uint4*)((p ? g_WtapL : g_WtapH) + k * 8192) + idx;
            *((uint4*)(smem + (p ? AL_OFF : AH_OFF)) + idx) = *src;
        }
        __syncthreads();

        int phase = k & 1, jt = k >> 1;
        uint32_t bRowBase =
            (uint32_t)((phase ? 72 : 0) + jt + wn * 16 + (lane & 7)) * 128;
        uint32_t xorB = (uint32_t)(((jt + (lane & 7)) & 7) << 4);

        #pragma unroll
        for (int ks = 0; ks < 4; ks++) {
            uint32_t cb = ((uint32_t)(ks * 32) + lb_col) ^ xorB;
            uint32_t bh[2][2], bl[2][2];
            #pragma unroll
            for (int nt = 0; nt < 2; nt++) {
                ldsm_x2(bh[nt], sbase + BH_OFF + bRowBase + nt * 1024 + cb);
                ldsm_x2(bl[nt], sbase + BL_OFF + bRowBase + nt * 1024 + cb);
            }
            uint32_t ca = ((uint32_t)(ks * 32) + la_col) ^ xorA;
            #pragma unroll
            for (int mt = 0; mt < 4; mt++) {
                uint32_t ah[4], al[4];
                ldsm_x4(ah, sbase + AH_OFF + aRow + mt * 2048 + ca);
                ldsm_x4(al, sbase + AL_OFF + aRow + mt * 2048 + ca);
                #pragma unroll
                for (int nt = 0; nt < 2; nt++) {
                    mma_bf16(acc[mt][nt], ah, bh[nt]);
                    mma_bf16(acc[mt][nt], ah, bl[nt]);
                    mma_bf16(acc[mt][nt], al, bh[nt]);
                }
            }
        }
    }

    // epilogue: + beff[o][t]
    float* Out = g_xtcn + ((size_t)n * O_) * TOV_;
    int qr = lane >> 2, qc = (lane & 3) * 2;
    #pragma unroll
    for (int mt = 0; mt < 4; mt++) {
        #pragma unroll
        for (int hh = 0; hh < 2; hh++) {
            int o = wm * 64 + mt * 16 + qr + hh * 8;
            const float* be = g_beff + o * TO_;
            float* orow = Out + (size_t)o * TOV_;
            #pragma unroll
            for (int nt = 0; nt < 2; nt++) {
                int t = t0 + wn * 16 + nt * 8 + qc;
                if (t < TO_)     orow[t * V_ + v]       = acc[mt][nt][hh * 2 + 0] + be[t];
                if (t + 1 < TO_) orow[(t + 1) * V_ + v] = acc[mt][nt][hh * 2 + 1] + be[t + 1];
            }
        }
    }
}

// ---------------------------------------------------------------------------
// K4: BN stats
// ---------------------------------------------------------------------------
__global__ void __launch_bounds__(256) k_stats(const float* __restrict__ gamma,
                                               const float* __restrict__ beta) {
    __shared__ double sh[512];
    int o = blockIdx.x;
    double s = 0.0, s2 = 0.0;
    for (int nn = 0; nn < N_; nn++) {
        const float* p = g_xtcn + ((size_t)nn * O_ + o) * TOV_;
        for (int i = threadIdx.x; i < TOV_; i += 256) {
            float v = p[i];
            s  += (double)v;
            s2 += (double)v * (double)v;
        }
    }
    sh[threadIdx.x] = s;
    sh[256 + threadIdx.x] = s2;
    __syncthreads();
    for (int st = 128; st > 0; st >>= 1) {
        if (threadIdx.x < st) {
            sh[threadIdx.x] += sh[threadIdx.x + st];
            sh[256 + threadIdx.x] += sh[256 + threadIdx.x + st];
        }
        __syncthreads();
    }
    if (threadIdx.x == 0) {
        double cnt = (double)N_ * (double)TOV_;
        double mean = sh[0] / cnt;
        double var = sh[256] / cnt - mean * mean;
        float rstd = (float)(1.0 / sqrt(var + 1e-5));
        float sc = gamma[o] * rstd;
        g_scale[o] = sc;
        g_shift[o] = beta[o] - (float)mean * sc;
    }
}

// ---------------------------------------------------------------------------
// K5: final — residual GEMM fused with BN affine + add + ReLU
// ---------------------------------------------------------------------------
__global__ void __launch_bounds__(256) k_final(const float* __restrict__ x,
                                               const float* __restrict__ W,
                                               const float* __restrict__ bias,
                                               float* __restrict__ out) {
    __shared__ float Wt[C_][132];
    __shared__ float Is[16][128];
    __shared__ int st2[128];
    __shared__ int sv[128];
    int tid = threadIdx.x;
    int n = blockIdx.y;
    int s0 = blockIdx.x * 128;
    const float* In = x + (size_t)n * C_ * TV_;

    #pragma unroll
    for (int i = 0; i < 32; i++) {
        int e = i * 256 + tid;
        int c = e & 63, o = e >> 6;
        Wt[c][o] = W[o * C_ + c];
    }
    if (tid < 128) {
        int s = s0 + tid;
        if (s < TOV_) { st2[tid] = (s / V_) * 2; sv[tid] = s % V_; }
        else          { st2[tid] = 0;            sv[tid] = 0; }
    }
    __syncthreads();

    int myS = tid & 127;
    int my_t2 = st2[myS];
    int my_v  = sv[myS];
    int kk_par = tid >> 7;
    int tx = tid & 15, ty = tid >> 4;
    float acc[8][8] = {};

    for (int kt = 0; kt < 4; kt++) {
        __syncthreads();
        #pragma unroll
        for (int i = 0; i < 8; i++) {
            int cl = 2 * i + kk_par;
            int c = kt * 16 + cl;
            Is[cl][myS] = In[(c * T_ + my_t2) * V_ + my_v];
        }
        __syncthreads();
        #pragma unroll
        for (int c = 0; c < 16; c++) {
            float4 a0 = *(const float4*)&Wt[kt * 16 + c][ty * 4];
            float4 a1 = *(const float4*)&Wt[kt * 16 + c][64 + ty * 4];
            float4 b0 = *(const float4*)&Is[c][tx * 4];
            float4 b1 = *(const float4*)&Is[c][64 + tx * 4];
            float a[8] = {a0.x, a0.y, a0.z, a0.w, a1.x, a1.y, a1.z, a1.w};
            float b[8] = {b0.x, b0.y, b0.z, b0.w, b1.x, b1.y, b1.z, b1.w};
            #pragma unroll
            for (int i = 0; i < 8; i++)
                #pragma unroll
                for (int j = 0; j < 8; j++)
                    acc[i][j] += a[i] * b[j];
        }
    }

    const float* Tcn = g_xtcn + (size_t)n * O_ * TOV_;
    #pragma unroll
    for (int i = 0; i < 8; i++) {
        int o = (i < 4) ? (ty * 4 + i) : (64 + ty * 4 + i - 4);
        float bo = __ldg(&bias[o]);
        float sc = g_scale[o];
        float sh = g_shift[o];
        #pragma unroll
        for (int j = 0; j < 8; j++) {
            int s = s0 + ((j < 4) ? (tx * 4 + j) : (64 + tx * 4 + j - 4));
            if (s < TOV_) {
                float bn = Tcn[o * TOV_ + s] * sc + sh;
                float v = bn + acc[i][j] + bo;
                out[((size_t)n * O_ + o) * TOV_ + s] = fmaxf(v, 0.f);
            }
        }
    }
}

// ---------------------------------------------------------------------------
extern "C" void kernel_launch(void* const* d_in, const int* in_sizes, int n_in,
                              void* d_out, int out_size) {
    const float* x       = (const float*)d_in[0];
    const float* A_parts = (const float*)d_in[1];
    const float* ei      = (const float*)d_in[2];
    const float* gcn_w   = (const float*)d_in[3];
    const float* gcn_b   = (const float*)d_in[4];
    const float* tcn_w   = (const float*)d_in[5];
    const float* tcn_b   = (const float*)d_in[6];
    const float* bn_g    = (const float*)d_in[7];
    const float* bn_b    = (const float*)d_in[8];
    const float* res_w   = (const float*)d_in[9];
    const float* res_b   = (const float*)d_in[10];
    float* out = (float*)d_out;

    cudaFuncSetAttribute(k_tcn_mma, cudaFuncAttributeMaxDynamicSharedMemorySize,
                         SMEM_TOT);

    k_asum<<<1, 640>>>(A_parts, ei);
    dim3 gagg(ROWS_, N_);
    k_aggp<<<gagg, 256>>>(x);
    k_weff<<<KKE_, 128>>>(tcn_w, gcn_w);
    k_beff<<<O_, 128>>>(tcn_w, gcn_b, tcn_b);
    k_wtap<<<9, 256>>>();
    dim3 gtcn(3, V_, N_);
    k_tcn_mma<<<gtcn, 256, SMEM_TOT>>>();
    k_stats<<<O_, 256>>>(bn_g, bn_b);
    dim3 gfin((TOV_ + 127) / 128, N_);
    k_final<<<gfin, 256>>>(x, res_w, res_b, out);
}

// round 7
// speedup vs baseline: 1.7867x; 1.2251x over previous
#include <cuda_runtime.h>
#include <cuda_bf16.h>
#include <cstdint>

// Problem constants
#define N_   32
#define C_   64
#define T_   300
#define V_   25
#define O_   128
#define TO_  150
#define TV_  7500
#define TOV_ 3750
#define KT_  9

// Phase-split transposed agg layout: [n][v][row][c], row<224: even phase
// (t_in = 2*(row-2)), row>=224: odd phase (t_in = 2*(row-224-2)+1).
#define ROWS_ 448

__device__ float g_xtcn[N_ * O_ * TO_ * V_];         // 61.4 MB fp32
__device__ float g_beff[O_ * TO_];
__device__ __align__(16) unsigned short g_aggBH[(size_t)N_ * V_ * ROWS_ * 64];
__device__ __align__(16) unsigned short g_aggBL[(size_t)N_ * V_ * ROWS_ * 64];
__device__ __align__(16) unsigned short g_WtapH[9 * 128 * 64];
__device__ __align__(16) unsigned short g_WtapL[9 * 128 * 64];
__device__ double g_sum[O_];
__device__ double g_sum2[O_];
__device__ float g_scale[O_];
__device__ float g_shift[O_];

// ---------------- PTX helpers ------------------------------------------------
__device__ __forceinline__ uint32_t smem_u32(const void* p) {
    uint32_t a;
    asm("{ .reg .u64 t; cvta.to.shared.u64 t, %1; cvt.u32.u64 %0, t; }" : "=r"(a) : "l"(p));
    return a;
}
__device__ __forceinline__ void ldsm_x4(uint32_t* r, uint32_t addr) {
    asm volatile("ldmatrix.sync.aligned.m8n8.x4.shared.b16 {%0,%1,%2,%3}, [%4];"
                 : "=r"(r[0]), "=r"(r[1]), "=r"(r[2]), "=r"(r[3]) : "r"(addr));
}
__device__ __forceinline__ void ldsm_x2(uint32_t* r, uint32_t addr) {
    asm volatile("ldmatrix.sync.aligned.m8n8.x2.shared.b16 {%0,%1}, [%2];"
                 : "=r"(r[0]), "=r"(r[1]) : "r"(addr));
}
__device__ __forceinline__ void mma_bf16(float* d, const uint32_t* a, const uint32_t* b) {
    asm volatile(
        "mma.sync.aligned.m16n8k16.row.col.f32.bf16.bf16.f32 "
        "{%0,%1,%2,%3}, {%4,%5,%6,%7}, {%8,%9}, {%0,%1,%2,%3};"
        : "+f"(d[0]), "+f"(d[1]), "+f"(d[2]), "+f"(d[3])
        : "r"(a[0]), "r"(a[1]), "r"(a[2]), "r"(a[3]), "r"(b[0]), "r"(b[1]));
}
#define SWZ128(x) ((x) ^ (((x) >> 3) & 0x70))

// ---------------------------------------------------------------------------
// L1: k_wprep — W_eff value computed and written directly as swizzled bf16
// hi/lo per-tap images. grid=576 (c,k), block=128 (o).
// ---------------------------------------------------------------------------
__global__ void __launch_bounds__(128) k_wprep(const float* __restrict__ tcn_w,
                                               const float* __restrict__ gcn_w) {
    __shared__ float gc[O_];
    int ck = blockIdx.x;
    int c = ck / KT_, k = ck % KT_;
    int o = threadIdx.x;
    gc[o] = gcn_w[o * C_ + c];
    __syncthreads();
    const float* wrow = tcn_w + (size_t)o * O_ * KT_ + k;
    float s = 0.f;
    #pragma unroll 8
    for (int o2 = 0; o2 < O_; o2++) s += wrow[o2 * KT_] * gc[o2];
    __nv_bfloat16 h = __float2bfloat16(s);
    __nv_bfloat16 l = __float2bfloat16(s - __bfloat162float(h));
    uint32_t boff = SWZ128((uint32_t)(o * 128 + c * 2));
    g_WtapH[k * 8192 + (boff >> 1)] = *reinterpret_cast<unsigned short*>(&h);
    g_WtapL[k * 8192 + (boff >> 1)] = *reinterpret_cast<unsigned short*>(&l);
}

// ---------------------------------------------------------------------------
// L2: k_beff — bias_eff + zero stats accumulators (graph-replay safe)
// ---------------------------------------------------------------------------
__global__ void __launch_bounds__(128) k_beff(const float* __restrict__ tcn_w,
                                              const float* __restrict__ gcn_b,
                                              const float* __restrict__ tcn_b) {
    __shared__ float red[128];
    __shared__ float Bk[KT_];
    int o = blockIdx.x, o2 = threadIdx.x;
    if (o2 == 0) { g_sum[o] = 0.0; g_sum2[o] = 0.0; }
    float gb = gcn_b[o2];
    const float* wrow = tcn_w + ((size_t)o * O_ + o2) * KT_;
    #pragma unroll
    for (int k = 0; k < KT_; k++) {
        red[o2] = wrow[k] * gb;
        __syncthreads();
        for (int st = 64; st > 0; st >>= 1) {
            if (o2 < st) red[o2] += red[o2 + st];
            __syncthreads();
        }
        if (o2 == 0) Bk[k] = red[0];
        __syncthreads();
    }
    float tb = tcn_b[o];
    for (int t = threadIdx.x; t < TO_; t += 128) {
        float s = tb;
        #pragma unroll
        for (int k = 0; k < KT_; k++) {
            int tp = 2 * t + k - 4;
            if (tp >= 0 && tp < T_) s += Bk[k];
        }
        g_beff[o * TO_ + t] = s;
    }
}

// ---------------------------------------------------------------------------
// L3: k_aggp — agg in phase-split transposed bf16 hi/lo layout (asum inlined)
// ---------------------------------------------------------------------------
__global__ void __launch_bounds__(256) k_aggp(const float* __restrict__ x,
                                              const float* __restrict__ A_parts,
                                              const float* __restrict__ ei) {
    __shared__ float sx[1600];
    __shared__ float As[625];
    __shared__ __align__(16) unsigned short souts[2][1600];
    int row = blockIdx.x, n = blockIdx.y, tid = threadIdx.x;
    int phase = (row >= 224) ? 1 : 0;
    int e = phase ? (row - 224) : row;
    int t_in = 2 * (e - 2) + phase;
    bool valid = (t_in >= 0) && (t_in < T_);

    if (valid) {
        float e0 = ei[0], e1 = ei[1], e2 = ei[2];
        for (int i = tid; i < 625; i += 256)
            As[i] = A_parts[i] * e0 + A_parts[625 + i] * e1 + A_parts[1250 + i] * e2;
        const float* xb = x + ((size_t)n * C_) * TV_ + t_in * V_;
        for (int i = tid; i < 1600; i += 256) {
            int c = i / 25, w = i - c * 25;
            sx[i] = xb[c * TV_ + w];
        }
        __syncthreads();
        for (int i = tid; i < 1600; i += 256) {
            int v = i >> 6, c = i & 63;
            float s = 0.f;
            #pragma unroll
            for (int w = 0; w < 25; w++) s += sx[c * 25 + w] * As[w * 25 + v];
            __nv_bfloat16 h = __float2bfloat16(s);
            __nv_bfloat16 l = __float2bfloat16(s - __bfloat162float(h));
            souts[0][v * 64 + c] = *reinterpret_cast<unsigned short*>(&h);
            souts[1][v * 64 + c] = *reinterpret_cast<unsigned short*>(&l);
        }
        __syncthreads();
        int r7 = row & 7;
        for (int j = tid; j < 400; j += 256) {
            int v = j >> 4, qq = j & 15, arr = qq >> 3, q = qq & 7;
            uint4 val = *(const uint4*)&souts[arr][v * 64 + ((q ^ r7) << 3)];
            unsigned short* base = arr ? g_aggBL : g_aggBH;
            *((uint4*)(base + (((size_t)(n * 25 + v) * ROWS_ + row) << 6)) + q) = val;
        }
    } else {
        for (int j = tid; j < 400; j += 256) {
            int v = j >> 4, qq = j & 15, arr = qq >> 3, q = qq & 7;
            unsigned short* base = arr ? g_aggBL : g_aggBH;
            *((uint4*)(base + (((size_t)(n * 25 + v) * ROWS_ + row) << 6)) + q) =
                make_uint4(0, 0, 0, 0);
        }
    }
}

// ---------------------------------------------------------------------------
// L4 (profiled slot): k_tcn_mma — tap-shift HMMA, 2 v per CTA (N=128),
// fused BN-stats accumulation in epilogue.
// smem: B hi [4 sec x 72 rows x 128B] | B lo | A hi 16KB | A lo 16KB
// ---------------------------------------------------------------------------
#define R_SEC  72
#define SEC_B  (R_SEC * 128)          // 9216
#define BH_OFF 0
#define BL_OFF (4 * SEC_B)            // 36864
#define AH_OFF (8 * SEC_B)            // 73728
#define AL_OFF (AH_OFF + 16384)       // 90112
#define SMEM_TOT (AL_OFF + 16384)     // 106496

__global__ void __launch_bounds__(256, 2) k_tcn_mma() {
    extern __shared__ __align__(16) unsigned char smem[];
    int tid = threadIdx.x, lane = tid & 31, wid = tid >> 5;
    int wm = wid >> 2, wn = wid & 3;
    int t0 = blockIdx.x * 64;
    int v0 = blockIdx.y * 2;
    int n = blockIdx.z;
    uint32_t sbase = smem_u32(smem);

    // ---- B copy: 4 sections (vsec,phase) x 72 rows; pad rows / invalid v -> 0
    for (int j = tid; j < 4608; j += 256) {
        int arr = (j >= 2304) ? 1 : 0;
        int r = arr ? (j - 2304) : j;
        int sec = r / 576;
        int rq = r - sec * 576;
        int row = rq >> 3, q = rq & 7;
        int vsec = sec >> 1, phase = sec & 1;
        int vv = v0 + vsec;
        uint4 val = make_uint4(0, 0, 0, 0);
        if (row < 68 && vv < V_) {
            int grow = (phase ? 224 : 0) + t0 + row;
            const unsigned short* g = (arr ? g_aggBL : g_aggBH) +
                (((size_t)(n * V_ + vv) * ROWS_ + grow) << 6);
            val = *((const uint4*)g + q);
        }
        *((uint4*)(smem + (arr ? BL_OFF : BH_OFF) + sec * SEC_B + row * 128) + q) = val;
    }

    // fragment addressing
    int la_row = ((lane >> 3) & 1) * 8 + (lane & 7);
    uint32_t xorA = (uint32_t)((lane & 7) << 4);
    uint32_t la_col = ((lane >> 4) & 1) * 16;
    uint32_t lb_col = ((lane >> 3) & 1) * 16;
    uint32_t aRow = (uint32_t)(wm * 64 + la_row) * 128;
    int vsec_w = wn >> 1, trow = (wn & 1) * 32;

    float acc[4][4][4] = {};

    for (int k = 0; k < 9; k++) {
        __syncthreads();
        // A tap copy (hi+lo, 32KB)
        for (int j = tid; j < 2048; j += 256) {
            int p = j >> 10, idx = j & 1023;
            *((uint4*)(smem + (p ? AL_OFF : AH_OFF)) + idx) =
                *((const uint4*)((p ? g_WtapL : g_WtapH) + k * 8192) + idx);
        }
        __syncthreads();

        int phase = k & 1, jt = k >> 1;
        uint32_t secoff = (uint32_t)(vsec_w * 2 + phase) * SEC_B;
        uint32_t rbase = (uint32_t)(jt + trow + (lane & 7));
        uint32_t xorB = (uint32_t)(((jt + (lane & 7)) & 7) << 4);

        #pragma unroll
        for (int ks = 0; ks < 4; ks++) {
            uint32_t cb = ((uint32_t)(ks * 32) + lb_col) ^ xorB;
            uint32_t bh[4][2], bl[4][2];
            #pragma unroll
            for (int nt = 0; nt < 4; nt++) {
                uint32_t ro = secoff + (rbase + nt * 8) * 128;
                ldsm_x2(bh[nt], sbase + BH_OFF + ro + cb);
                ldsm_x2(bl[nt], sbase + BL_OFF + ro + cb);
            }
            uint32_t ca = ((uint32_t)(ks * 32) + la_col) ^ xorA;
            #pragma unroll
            for (int mt = 0; mt < 4; mt++) {
                uint32_t ah[4], al[4];
                ldsm_x4(ah, sbase + AH_OFF + aRow + mt * 2048 + ca);
                ldsm_x4(al, sbase + AL_OFF + aRow + mt * 2048 + ca);
                #pragma unroll
                for (int nt = 0; nt < 4; nt++) {
                    mma_bf16(acc[mt][nt], ah, bh[nt]);
                    mma_bf16(acc[mt][nt], ah, bl[nt]);
                    mma_bf16(acc[mt][nt], al, bh[nt]);
                }
            }
        }
    }

    // ---- epilogue + fused stats (smem reuse is safe after last ldsm+sync)
    __syncthreads();
    float* ssum = (float*)smem;
    float* ssum2 = ssum + 128;
    if (tid < 128) { ssum[tid] = 0.f; ssum2[tid] = 0.f; }
    __syncthreads();

    float* Out = g_xtcn + (size_t)n * O_ * TOV_;
    int qr = lane >> 2, qc = (lane & 3) * 2;
    int vv = v0 + vsec_w;
    #pragma unroll
    for (int mt = 0; mt < 4; mt++) {
        #pragma unroll
        for (int hh = 0; hh < 2; hh++) {
            int o = wm * 64 + mt * 16 + qr + hh * 8;
            const float* be = g_beff + o * TO_;
            float* orow = Out + (size_t)o * TOV_;
            float s1 = 0.f, s2 = 0.f;
            #pragma unroll
            for (int nt = 0; nt < 4; nt++) {
                int t = t0 + trow + nt * 8 + qc;
                if (vv < V_) {
                    if (t < TO_) {
                        float y = acc[mt][nt][hh * 2 + 0] + be[t];
                        orow[t * V_ + vv] = y;
                        s1 += y; s2 += y * y;
                    }
                    if (t + 1 < TO_) {
                        float y = acc[mt][nt][hh * 2 + 1] + be[t + 1];
                        orow[(t + 1) * V_ + vv] = y;
                        s1 += y; s2 += y * y;
                    }
                }
            }
            s1 += __shfl_xor_sync(0xFFFFFFFFu, s1, 1);
            s1 += __shfl_xor_sync(0xFFFFFFFFu, s1, 2);
            s2 += __shfl_xor_sync(0xFFFFFFFFu, s2, 1);
            s2 += __shfl_xor_sync(0xFFFFFFFFu, s2, 2);
            if ((lane & 3) == 0) {
                atomicAdd(&ssum[o], s1);
                atomicAdd(&ssum2[o], s2);
            }
        }
    }
    __syncthreads();
    if (tid < 128) {
        atomicAdd(&g_sum[tid], (double)ssum[tid]);
        atomicAdd(&g_sum2[tid], (double)ssum2[tid]);
    }
}

// ---------------------------------------------------------------------------
// L5: k_statsfin — finalize BN scale/shift
// ---------------------------------------------------------------------------
__global__ void k_statsfin(const float* __restrict__ gamma,
                           const float* __restrict__ beta) {
    int o = threadIdx.x;
    double cnt = (double)N_ * (double)TOV_;
    double mean = g_sum[o] / cnt;
    double var = g_sum2[o] / cnt - mean * mean;
    float rstd = (float)(1.0 / sqrt(var + 1e-5));
    float sc = gamma[o] * rstd;
    g_scale[o] = sc;
    g_shift[o] = beta[o] - (float)mean * sc;
}

// ---------------------------------------------------------------------------
// L6: k_final — residual GEMM fused with BN affine + add + ReLU
// ---------------------------------------------------------------------------
__global__ void __launch_bounds__(256) k_final(const float* __restrict__ x,
                                               const float* __restrict__ W,
                                               const float* __restrict__ bias,
                                               float* __restrict__ out) {
    __shared__ float Wt[C_][132];
    __shared__ float Is[16][128];
    __shared__ int st2[128];
    __shared__ int sv[128];
    int tid = threadIdx.x;
    int n = blockIdx.y;
    int s0 = blockIdx.x * 128;
    const float* In = x + (size_t)n * C_ * TV_;

    #pragma unroll
    for (int i = 0; i < 32; i++) {
        int e = i * 256 + tid;
        int c = e & 63, o = e >> 6;
        Wt[c][o] = W[o * C_ + c];
    }
    if (tid < 128) {
        int s = s0 + tid;
        if (s < TOV_) { st2[tid] = (s / V_) * 2; sv[tid] = s % V_; }
        else          { st2[tid] = 0;            sv[tid] = 0; }
    }
    __syncthreads();

    int myS = tid & 127;
    int my_t2 = st2[myS];
    int my_v  = sv[myS];
    int kk_par = tid >> 7;
    int tx = tid & 15, ty = tid >> 4;
    float acc[8][8] = {};

    for (int kt = 0; kt < 4; kt++) {
        __syncthreads();
        #pragma unroll
        for (int i = 0; i < 8; i++) {
            int cl = 2 * i + kk_par;
            int c = kt * 16 + cl;
            Is[cl][myS] = In[(c * T_ + my_t2) * V_ + my_v];
        }
        __syncthreads();
        #pragma unroll
        for (int c = 0; c < 16; c++) {
            float4 a0 = *(const float4*)&Wt[kt * 16 + c][ty * 4];
            float4 a1 = *(const float4*)&Wt[kt * 16 + c][64 + ty * 4];
            float4 b0 = *(const float4*)&Is[c][tx * 4];
            float4 b1 = *(const float4*)&Is[c][64 + tx * 4];
            float a[8] = {a0.x, a0.y, a0.z, a0.w, a1.x, a1.y, a1.z, a1.w};
            float b[8] = {b0.x, b0.y, b0.z, b0.w, b1.x, b1.y, b1.z, b1.w};
            #pragma unroll
            for (int i = 0; i < 8; i++)
                #pragma unroll
                for (int j = 0; j < 8; j++)
                    acc[i][j] += a[i] * b[j];
        }
    }

    const float* Tcn = g_xtcn + (size_t)n * O_ * TOV_;
    #pragma unroll
    for (int i = 0; i < 8; i++) {
        int o = (i < 4) ? (ty * 4 + i) : (64 + ty * 4 + i - 4);
        float bo = __ldg(&bias[o]);
        float sc = g_scale[o];
        float sh = g_shift[o];
        #pragma unroll
        for (int j = 0; j < 8; j++) {
            int s = s0 + ((j < 4) ? (tx * 4 + j) : (64 + tx * 4 + j - 4));
            if (s < TOV_) {
                float bn = Tcn[o * TOV_ + s] * sc + sh;
                float v = bn + acc[i][j] + bo;
                out[((size_t)n * O_ + o) * TOV_ + s] = fmaxf(v, 0.f);
            }
        }
    }
}

// ---------------------------------------------------------------------------
extern "C" void kernel_launch(void* const* d_in, const int* in_sizes, int n_in,
                              void* d_out, int out_size) {
    const float* x       = (const float*)d_in[0];
    const float* A_parts = (const float*)d_in[1];
    const float* ei      = (const float*)d_in[2];
    const float* gcn_w   = (const float*)d_in[3];
    const float* gcn_b   = (const float*)d_in[4];
    const float* tcn_w   = (const float*)d_in[5];
    const float* tcn_b   = (const float*)d_in[6];
    const float* bn_g    = (const float*)d_in[7];
    const float* bn_b    = (const float*)d_in[8];
    const float* res_w   = (const float*)d_in[9];
    const float* res_b   = (const float*)d_in[10];
    float* out = (float*)d_out;

    cudaFuncSetAttribute(k_tcn_mma, cudaFuncAttributeMaxDynamicSharedMemorySize,
                         SMEM_TOT);

    k_wprep<<<576, 128>>>(tcn_w, gcn_w);                 // 1
    k_beff<<<O_, 128>>>(tcn_w, gcn_b, tcn_b);            // 2
    dim3 gagg(ROWS_, N_);
    k_aggp<<<gagg, 256>>>(x, A_parts, ei);               // 3
    dim3 gtcn(3, 13, N_);
    k_tcn_mma<<<gtcn, 256, SMEM_TOT>>>();                // 4  <- profiled
    k_statsfin<<<1, 128>>>(bn_g, bn_b);                  // 5
    dim3 gfin((TOV_ + 127) / 128, N_);
    k_final<<<gfin, 256>>>(x, res_w, res_b, out);        // 6
}

// round 8
// speedup vs baseline: 1.7868x; 1.0001x over previous
#include <cuda_runtime.h>
#include <cuda_bf16.h>
#include <cstdint>

// Problem constants
#define N_   32
#define C_   64
#define T_   300
#define V_   25
#define O_   128
#define TO_  150
#define TV_  7500
#define TOV_ 3750
#define KT_  9

// Phase-split transposed agg layout: [n][v][row][c], row<224: even phase
// (t_in = 2*(row-2)), row>=224: odd phase (t_in = 2*(row-224-2)+1).
#define ROWS_ 448

__device__ float g_xtcn[N_ * O_ * TO_ * V_];         // 61.4 MB fp32
__device__ float g_beff[O_ * TO_];
__device__ __align__(16) unsigned short g_aggBH[(size_t)N_ * V_ * ROWS_ * 64];
__device__ __align__(16) unsigned short g_aggBL[(size_t)N_ * V_ * ROWS_ * 64];
__device__ __align__(16) unsigned short g_WtapH[9 * 128 * 64];
__device__ __align__(16) unsigned short g_WtapL[9 * 128 * 64];
__device__ double g_sum[O_];
__device__ double g_sum2[O_];
__device__ float g_scale[O_];
__device__ float g_shift[O_];

// ---------------- PTX helpers ------------------------------------------------
__device__ __forceinline__ uint32_t smem_u32(const void* p) {
    uint32_t a;
    asm("{ .reg .u64 t; cvta.to.shared.u64 t, %1; cvt.u32.u64 %0, t; }" : "=r"(a) : "l"(p));
    return a;
}
__device__ __forceinline__ void ldsm_x4(uint32_t* r, uint32_t addr) {
    asm volatile("ldmatrix.sync.aligned.m8n8.x4.shared.b16 {%0,%1,%2,%3}, [%4];"
                 : "=r"(r[0]), "=r"(r[1]), "=r"(r[2]), "=r"(r[3]) : "r"(addr));
}
__device__ __forceinline__ void ldsm_x2(uint32_t* r, uint32_t addr) {
    asm volatile("ldmatrix.sync.aligned.m8n8.x2.shared.b16 {%0,%1}, [%2];"
                 : "=r"(r[0]), "=r"(r[1]) : "r"(addr));
}
__device__ __forceinline__ void mma_bf16(float* d, const uint32_t* a, const uint32_t* b) {
    asm volatile(
        "mma.sync.aligned.m16n8k16.row.col.f32.bf16.bf16.f32 "
        "{%0,%1,%2,%3}, {%4,%5,%6,%7}, {%8,%9}, {%0,%1,%2,%3};"
        : "+f"(d[0]), "+f"(d[1]), "+f"(d[2]), "+f"(d[3])
        : "r"(a[0]), "r"(a[1]), "r"(a[2]), "r"(a[3]), "r"(b[0]), "r"(b[1]));
}
#define SWZ128(x) ((x) ^ (((x) >> 3) & 0x70))

// ---------------------------------------------------------------------------
// L1: k_wprep — W_eff value computed and written directly as swizzled bf16
// hi/lo per-tap images. grid=576 (c,k), block=128 (o).
// ---------------------------------------------------------------------------
__global__ void __launch_bounds__(128) k_wprep(const float* __restrict__ tcn_w,
                                               const float* __restrict__ gcn_w) {
    __shared__ float gc[O_];
    int ck = blockIdx.x;
    int c = ck / KT_, k = ck % KT_;
    int o = threadIdx.x;
    gc[o] = gcn_w[o * C_ + c];
    __syncthreads();
    const float* wrow = tcn_w + (size_t)o * O_ * KT_ + k;
    float s = 0.f;
    #pragma unroll 8
    for (int o2 = 0; o2 < O_; o2++) s += wrow[o2 * KT_] * gc[o2];
    __nv_bfloat16 h = __float2bfloat16(s);
    __nv_bfloat16 l = __float2bfloat16(s - __bfloat162float(h));
    uint32_t boff = SWZ128((uint32_t)(o * 128 + c * 2));
    g_WtapH[k * 8192 + (boff >> 1)] = *reinterpret_cast<unsigned short*>(&h);
    g_WtapL[k * 8192 + (boff >> 1)] = *reinterpret_cast<unsigned short*>(&l);
}

// ---------------------------------------------------------------------------
// L2: k_beff — bias_eff + zero stats accumulators (graph-replay safe)
// ---------------------------------------------------------------------------
__global__ void __launch_bounds__(128) k_beff(const float* __restrict__ tcn_w,
                                              const float* __restrict__ gcn_b,
                                              const float* __restrict__ tcn_b) {
    __shared__ float red[128];
    __shared__ float Bk[KT_];
    int o = blockIdx.x, o2 = threadIdx.x;
    if (o2 == 0) { g_sum[o] = 0.0; g_sum2[o] = 0.0; }
    float gb = gcn_b[o2];
    const float* wrow = tcn_w + ((size_t)o * O_ + o2) * KT_;
    #pragma unroll
    for (int k = 0; k < KT_; k++) {
        red[o2] = wrow[k] * gb;
        __syncthreads();
        for (int st = 64; st > 0; st >>= 1) {
            if (o2 < st) red[o2] += red[o2 + st];
            __syncthreads();
        }
        if (o2 == 0) Bk[k] = red[0];
        __syncthreads();
    }
    float tb = tcn_b[o];
    for (int t = threadIdx.x; t < TO_; t += 128) {
        float s = tb;
        #pragma unroll
        for (int k = 0; k < KT_; k++) {
            int tp = 2 * t + k - 4;
            if (tp >= 0 && tp < T_) s += Bk[k];
        }
        g_beff[o * TO_ + t] = s;
    }
}

// ---------------------------------------------------------------------------
// L3: k_aggp — agg in phase-split transposed bf16 hi/lo layout (asum inlined)
// ---------------------------------------------------------------------------
__global__ void __launch_bounds__(256) k_aggp(const float* __restrict__ x,
                                              const float* __restrict__ A_parts,
                                              const float* __restrict__ ei) {
    __shared__ float sx[1600];
    __shared__ float As[625];
    __shared__ __align__(16) unsigned short souts[2][1600];
    int row = blockIdx.x, n = blockIdx.y, tid = threadIdx.x;
    int phase = (row >= 224) ? 1 : 0;
    int e = phase ? (row - 224) : row;
    int t_in = 2 * (e - 2) + phase;
    bool valid = (t_in >= 0) && (t_in < T_);

    if (valid) {
        float e0 = ei[0], e1 = ei[1], e2 = ei[2];
        for (int i = tid; i < 625; i += 256)
            As[i] = A_parts[i] * e0 + A_parts[625 + i] * e1 + A_parts[1250 + i] * e2;
        const float* xb = x + ((size_t)n * C_) * TV_ + t_in * V_;
        for (int i = tid; i < 1600; i += 256) {
            int c = i / 25, w = i - c * 25;
            sx[i] = xb[c * TV_ + w];
        }
        __syncthreads();
        for (int i = tid; i < 1600; i += 256) {
            int v = i >> 6, c = i & 63;
            float s = 0.f;
            #pragma unroll
            for (int w = 0; w < 25; w++) s += sx[c * 25 + w] * As[w * 25 + v];
            __nv_bfloat16 h = __float2bfloat16(s);
            __nv_bfloat16 l = __float2bfloat16(s - __bfloat162float(h));
            souts[0][v * 64 + c] = *reinterpret_cast<unsigned short*>(&h);
            souts[1][v * 64 + c] = *reinterpret_cast<unsigned short*>(&l);
        }
        __syncthreads();
        int r7 = row & 7;
        for (int j = tid; j < 400; j += 256) {
            int v = j >> 4, qq = j & 15, arr = qq >> 3, q = qq & 7;
            uint4 val = *(const uint4*)&souts[arr][v * 64 + ((q ^ r7) << 3)];
            unsigned short* base = arr ? g_aggBL : g_aggBH;
            *((uint4*)(base + (((size_t)(n * 25 + v) * ROWS_ + row) << 6)) + q) = val;
        }
    } else {
        for (int j = tid; j < 400; j += 256) {
            int v = j >> 4, qq = j & 15, arr = qq >> 3, q = qq & 7;
            unsigned short* base = arr ? g_aggBL : g_aggBH;
            *((uint4*)(base + (((size_t)(n * 25 + v) * ROWS_ + row) << 6)) + q) =
                make_uint4(0, 0, 0, 0);
        }
    }
}

// ---------------------------------------------------------------------------
// L4 (profiled slot): k_tcn_mma — tap-shift HMMA, 2 v per CTA (N=128),
// fused BN-stats accumulation in epilogue.
// smem: B hi [4 sec x 72 rows x 128B] | B lo | A hi 16KB | A lo 16KB
// ---------------------------------------------------------------------------
#define R_SEC  72
#define SEC_B  (R_SEC * 128)          // 9216
#define BH_OFF 0
#define BL_OFF (4 * SEC_B)            // 36864
#define AH_OFF (8 * SEC_B)            // 73728
#define AL_OFF (AH_OFF + 16384)       // 90112
#define SMEM_TOT (AL_OFF + 16384)     // 106496

__global__ void __launch_bounds__(256, 2) k_tcn_mma() {
    extern __shared__ __align__(16) unsigned char smem[];
    int tid = threadIdx.x, lane = tid & 31, wid = tid >> 5;
    int wm = wid >> 2, wn = wid & 3;
    int t0 = blockIdx.x * 64;
    int v0 = blockIdx.y * 2;
    int n = blockIdx.z;
    uint32_t sbase = smem_u32(smem);

    // ---- B copy: 4 sections (vsec,phase) x 72 rows; pad rows / invalid v -> 0
    for (int j = tid; j < 4608; j += 256) {
        int arr = (j >= 2304) ? 1 : 0;
        int r = arr ? (j - 2304) : j;
        int sec = r / 576;
        int rq = r - sec * 576;
        int row = rq >> 3, q = rq & 7;
        int vsec = sec >> 1, phase = sec & 1;
        int vv = v0 + vsec;
        uint4 val = make_uint4(0, 0, 0, 0);
        if (row < 68 && vv < V_) {
            int grow = (phase ? 224 : 0) + t0 + row;
            const unsigned short* g = (arr ? g_aggBL : g_aggBH) +
                (((size_t)(n * V_ + vv) * ROWS_ + grow) << 6);
            val = *((const uint4*)g + q);
        }
        *((uint4*)(smem + (arr ? BL_OFF : BH_OFF) + sec * SEC_B + row * 128) + q) = val;
    }

    // fragment addressing
    int la_row = ((lane >> 3) & 1) * 8 + (lane & 7);
    uint32_t xorA = (uint32_t)((lane & 7) << 4);
    uint32_t la_col = ((lane >> 4) & 1) * 16;
    uint32_t lb_col = ((lane >> 3) & 1) * 16;
    uint32_t aRow = (uint32_t)(wm * 64 + la_row) * 128;
    int vsec_w = wn >> 1, trow = (wn & 1) * 32;

    float acc[4][4][4] = {};

    for (int k = 0; k < 9; k++) {
        __syncthreads();
        // A tap copy (hi+lo, 32KB)
        for (int j = tid; j < 2048; j += 256) {
            int p = j >> 10, idx = j & 1023;
            *((uint4*)(smem + (p ? AL_OFF : AH_OFF)) + idx) =
                *((const uint4*)((p ? g_WtapL : g_WtapH) + k * 8192) + idx);
        }
        __syncthreads();

        int phase = k & 1, jt = k >> 1;
        uint32_t secoff = (uint32_t)(vsec_w * 2 + phase) * SEC_B;
        uint32_t rbase = (uint32_t)(jt + trow + (lane & 7));
        uint32_t xorB = (uint32_t)(((jt + (lane & 7)) & 7) << 4);

        #pragma unroll
        for (int ks = 0; ks < 4; ks++) {
            uint32_t cb = ((uint32_t)(ks * 32) + lb_col) ^ xorB;
            uint32_t bh[4][2], bl[4][2];
            #pragma unroll
            for (int nt = 0; nt < 4; nt++) {
                uint32_t ro = secoff + (rbase + nt * 8) * 128;
                ldsm_x2(bh[nt], sbase + BH_OFF + ro + cb);
                ldsm_x2(bl[nt], sbase + BL_OFF + ro + cb);
            }
            uint32_t ca = ((uint32_t)(ks * 32) + la_col) ^ xorA;
            #pragma unroll
            for (int mt = 0; mt < 4; mt++) {
                uint32_t ah[4], al[4];
                ldsm_x4(ah, sbase + AH_OFF + aRow + mt * 2048 + ca);
                ldsm_x4(al, sbase + AL_OFF + aRow + mt * 2048 + ca);
                #pragma unroll
                for (int nt = 0; nt < 4; nt++) {
                    mma_bf16(acc[mt][nt], ah, bh[nt]);
                    mma_bf16(acc[mt][nt], ah, bl[nt]);
                    mma_bf16(acc[mt][nt], al, bh[nt]);
                }
            }
        }
    }

    // ---- epilogue + fused stats (smem reuse is safe after last ldsm+sync)
    __syncthreads();
    float* ssum = (float*)smem;
    float* ssum2 = ssum + 128;
    if (tid < 128) { ssum[tid] = 0.f; ssum2[tid] = 0.f; }
    __syncthreads();

    float* Out = g_xtcn + (size_t)n * O_ * TOV_;
    int qr = lane >> 2, qc = (lane & 3) * 2;
    int vv = v0 + vsec_w;
    #pragma unroll
    for (int mt = 0; mt < 4; mt++) {
        #pragma unroll
        for (int hh = 0; hh < 2; hh++) {
            int o = wm * 64 + mt * 16 + qr + hh * 8;
            const float* be = g_beff + o * TO_;
            float* orow = Out + (size_t)o * TOV_;
            float s1 = 0.f, s2 = 0.f;
            #pragma unroll
            for (int nt = 0; nt < 4; nt++) {
                int t = t0 + trow + nt * 8 + qc;
                if (vv < V_) {
                    if (t < TO_) {
                        float y = acc[mt][nt][hh * 2 + 0] + be[t];
                        orow[t * V_ + vv] = y;
                        s1 += y; s2 += y * y;
                    }
                    if (t + 1 < TO_) {
                        float y = acc[mt][nt][hh * 2 + 1] + be[t + 1];
                        orow[(t + 1) * V_ + vv] = y;
                        s1 += y; s2 += y * y;
                    }
                }
            }
            s1 += __shfl_xor_sync(0xFFFFFFFFu, s1, 1);
            s1 += __shfl_xor_sync(0xFFFFFFFFu, s1, 2);
            s2 += __shfl_xor_sync(0xFFFFFFFFu, s2, 1);
            s2 += __shfl_xor_sync(0xFFFFFFFFu, s2, 2);
            if ((lane & 3) == 0) {
                atomicAdd(&ssum[o], s1);
                atomicAdd(&ssum2[o], s2);
            }
        }
    }
    __syncthreads();
    if (tid < 128) {
        atomicAdd(&g_sum[tid], (double)ssum[tid]);
        atomicAdd(&g_sum2[tid], (double)ssum2[tid]);
    }
}

// ---------------------------------------------------------------------------
// L5: k_statsfin — finalize BN scale/shift
// ---------------------------------------------------------------------------
__global__ void k_statsfin(const float* __restrict__ gamma,
                           const float* __restrict__ beta) {
    int o = threadIdx.x;
    double cnt = (double)N_ * (double)TOV_;
    double mean = g_sum[o] / cnt;
    double var = g_sum2[o] / cnt - mean * mean;
    float rstd = (float)(1.0 / sqrt(var + 1e-5));
    float sc = gamma[o] * rstd;
    g_scale[o] = sc;
    g_shift[o] = beta[o] - (float)mean * sc;
}

// ---------------------------------------------------------------------------
// L6: k_final — residual GEMM fused with BN affine + add + ReLU
// ---------------------------------------------------------------------------
__global__ void __launch_bounds__(256) k_final(const float* __restrict__ x,
                                               const float* __restrict__ W,
                                               const float* __restrict__ bias,
                                               float* __restrict__ out) {
    __shared__ float Wt[C_][132];
    __shared__ float Is[16][128];
    __shared__ int st2[128];
    __shared__ int sv[128];
    int tid = threadIdx.x;
    int n = blockIdx.y;
    int s0 = blockIdx.x * 128;
    const float* In = x + (size_t)n * C_ * TV_;

    #pragma unroll
    for (int i = 0; i < 32; i++) {
        int e = i * 256 + tid;
        int c = e & 63, o = e >> 6;
        Wt[c][o] = W[o * C_ + c];
    }
    if (tid < 128) {
        int s = s0 + tid;
        if (s < TOV_) { st2[tid] = (s / V_) * 2; sv[tid] = s % V_; }
        else          { st2[tid] = 0;            sv[tid] = 0; }
    }
    __syncthreads();

    int myS = tid & 127;
    int my_t2 = st2[myS];
    int my_v  = sv[myS];
    int kk_par = tid >> 7;
    int tx = tid & 15, ty = tid >> 4;
    float acc[8][8] = {};

    for (int kt = 0; kt < 4; kt++) {
        __syncthreads();
        #pragma unroll
        for (int i = 0; i < 8; i++) {
            int cl = 2 * i + kk_par;
            int c = kt * 16 + cl;
            Is[cl][myS] = In[(c * T_ + my_t2) * V_ + my_v];
        }
        __syncthreads();
        #pragma unroll
        for (int c = 0; c < 16; c++) {
            float4 a0 = *(const float4*)&Wt[kt * 16 + c][ty * 4];
            float4 a1 = *(const float4*)&Wt[kt * 16 + c][64 + ty * 4];
            float4 b0 = *(const float4*)&Is[c][tx * 4];
            float4 b1 = *(const float4*)&Is[c][64 + tx * 4];
            float a[8] = {a0.x, a0.y, a0.z, a0.w, a1.x, a1.y, a1.z, a1.w};
            float b[8] = {b0.x, b0.y, b0.z, b0.w, b1.x, b1.y, b1.z, b1.w};
            #pragma unroll
            for (int i = 0; i < 8; i++)
                #pragma unroll
                for (int j = 0; j < 8; j++)
                    acc[i][j] += a[i] * b[j];
        }
    }

    const float* Tcn = g_xtcn + (size_t)n * O_ * TOV_;
    #pragma unroll
    for (int i = 0; i < 8; i++) {
        int o = (i < 4) ? (ty * 4 + i) : (64 + ty * 4 + i - 4);
        float bo = __ldg(&bias[o]);
        float sc = g_scale[o];
        float sh = g_shift[o];
        #pragma unroll
        for (int j = 0; j < 8; j++) {
            int s = s0 + ((j < 4) ? (tx * 4 + j) : (64 + tx * 4 + j - 4));
            if (s < TOV_) {
                float bn = Tcn[o * TOV_ + s] * sc + sh;
                float v = bn + acc[i][j] + bo;
                out[((size_t)n * O_ + o) * TOV_ + s] = fmaxf(v, 0.f);
            }
        }
    }
}

// ---------------------------------------------------------------------------
extern "C" void kernel_launch(void* const* d_in, const int* in_sizes, int n_in,
                              void* d_out, int out_size) {
    const float* x       = (const float*)d_in[0];
    const float* A_parts = (const float*)d_in[1];
    const float* ei      = (const float*)d_in[2];
    const float* gcn_w   = (const float*)d_in[3];
    const float* gcn_b   = (const float*)d_in[4];
    const float* tcn_w   = (const float*)d_in[5];
    const float* tcn_b   = (const float*)d_in[6];
    const float* bn_g    = (const float*)d_in[7];
    const float* bn_b    = (const float*)d_in[8];
    const float* res_w   = (const float*)d_in[9];
    const float* res_b   = (const float*)d_in[10];
    float* out = (float*)d_out;

    cudaFuncSetAttribute(k_tcn_mma, cudaFuncAttributeMaxDynamicSharedMemorySize,
                         SMEM_TOT);

    k_wprep<<<576, 128>>>(tcn_w, gcn_w);                 // 1
    k_beff<<<O_, 128>>>(tcn_w, gcn_b, tcn_b);            // 2
    dim3 gagg(ROWS_, N_);
    k_aggp<<<gagg, 256>>>(x, A_parts, ei);               // 3
    dim3 gtcn(3, 13, N_);
    k_tcn_mma<<<gtcn, 256, SMEM_TOT>>>();                // 4  <- profiled
    k_statsfin<<<1, 128>>>(bn_g, bn_b);                  // 5
    dim3 gfin((TOV_ + 127) / 128, N_);
    k_final<<<gfin, 256>>>(x, res_w, res_b, out);        // 6
}